// round 1
// baseline (speedup 1.0000x reference)
#include <cuda_runtime.h>
#include <math.h>

#define NIMG 8
#define HH   768
#define WW   1024
#define HW   (HH * WW)
#define SS   30000
#define NBLK_S ((SS + 255) / 256)   // 118

// ---------------- device scratch (static, no runtime alloc) ----------------
__device__ float    g_edge [NIMG * HW];     // 25 MB
__device__ float    g_theta[NIMG * HW];     // 25 MB
__device__ int      g_list [NIMG * HW];     // 25 MB (worst case)
__device__ unsigned g_emax [NIMG];          // float bits (edges >= 0)
__device__ int      g_rowcnt[NIMG * HH];
__device__ int      g_rowoff[NIMG * HH];
__device__ int      g_total [NIMG];
__device__ float4   g_part4[NIMG][128];     // per-block partial sums (padded to 128)

// ---------------------------------------------------------------------------
__global__ void k_init() {
    int t = blockIdx.x * blockDim.x + threadIdx.x;   // 1024 threads total
    if (t < NIMG * 128) ((float4*)g_part4)[t] = make_float4(0.f, 0.f, 0.f, 0.f);
    if (t < NIMG) g_emax[t] = 0u;
}

// ---------------------------------------------------------------------------
// Sobel on channel 0 of images[N,3,H,W]; edges/thetas with zero border.
__global__ __launch_bounds__(256) void k_sobel(const float* __restrict__ images) {
    int n   = blockIdx.y;
    int idx = blockIdx.x * 256 + threadIdx.x;        // < HW
    const float* g = images + (size_t)n * 3 * HW;    // channel 0
    int y = idx >> 10, x = idx & 1023;

    float e = 0.f, th = 0.f;
    if (y >= 1 && y < HH - 1 && x >= 1 && x < WW - 1) {
        const float* r0 = g + (y - 1) * WW;
        const float* r1 = g + (y    ) * WW;
        const float* r2 = g + (y + 1) * WW;
        float a = r0[x - 1], b = r0[x], c = r0[x + 1];
        float d = r1[x - 1],            f = r1[x + 1];
        float p = r2[x - 1], q = r2[x], s = r2[x + 1];
        // cross-correlation with ka/kb (XLA conv semantics)
        float gx = (c - a) + 2.f * (f - d) + (s - p);
        float gy = (a + 2.f * b + c) - (p + 2.f * q + s);
        e  = sqrtf(gx * gx + gy * gy + 1e-6f);
        th = atan2f(gy, gx);
    }
    g_edge [n * HW + idx] = e;
    g_theta[n * HW + idx] = th;

    // block max -> atomicMax on uint bits (edges >= 0 so ordering matches)
    __shared__ float smax[256];
    smax[threadIdx.x] = e;
    __syncthreads();
    for (int o = 128; o > 0; o >>= 1) {
        if (threadIdx.x < o) smax[threadIdx.x] = fmaxf(smax[threadIdx.x], smax[threadIdx.x + o]);
        __syncthreads();
    }
    if (threadIdx.x == 0)
        atomicMax(&g_emax[n], __float_as_uint(smax[0]));
}

// ---------------------------------------------------------------------------
__global__ __launch_bounds__(1024) void k_rowcount() {
    int n = blockIdx.y, row = blockIdx.x, col = threadIdx.x;
    float thr = __uint_as_float(g_emax[n]) * 0.1f;
    int flag = (g_edge[n * HW + row * WW + col] >= thr) ? 1 : 0;
    int cnt = __syncthreads_count(flag);
    if (col == 0) g_rowcnt[n * HH + row] = cnt;
}

// ---------------------------------------------------------------------------
__global__ __launch_bounds__(1024) void k_rowscan() {
    __shared__ int sh[1024];
    int n = blockIdx.x, t = threadIdx.x;
    int v = (t < HH) ? g_rowcnt[n * HH + t] : 0;
    sh[t] = v;
    __syncthreads();
    for (int off = 1; off < 1024; off <<= 1) {
        int u = (t >= off) ? sh[t - off] : 0;
        __syncthreads();
        sh[t] += u;
        __syncthreads();
    }
    if (t < HH) g_rowoff[n * HH + t] = sh[t] - v;   // exclusive
    if (t == HH - 1) g_total[n] = sh[t];
}

// ---------------------------------------------------------------------------
// Stable (raster-order) compaction of edge-pixel flat indices.
__global__ __launch_bounds__(1024) void k_compact() {
    int n = blockIdx.y, row = blockIdx.x, col = threadIdx.x;
    float thr = __uint_as_float(g_emax[n]) * 0.1f;
    int flag = (g_edge[n * HW + row * WW + col] >= thr) ? 1 : 0;

    unsigned ball = __ballot_sync(0xffffffffu, flag);
    int lane = col & 31, wid = col >> 5;
    int wprefix = __popc(ball & ((1u << lane) - 1u));

    __shared__ int wtot[32], woff[32];
    if (lane == 0) wtot[wid] = __popc(ball);
    __syncthreads();
    if (wid == 0) {
        int v = wtot[lane];
        int inc = v;
        for (int o = 1; o < 32; o <<= 1) {
            int u = __shfl_up_sync(0xffffffffu, inc, o);
            if (lane >= o) inc += u;
        }
        woff[lane] = inc - v;
    }
    __syncthreads();

    if (flag) {
        int pos = g_rowoff[n * HH + row] + woff[wid] + wprefix;
        g_list[n * HW + pos] = row * WW + col;
    }
}

// ---------------------------------------------------------------------------
__device__ __forceinline__ float softplus_f(float x) {
    return fmaxf(x, 0.f) + log1pf(expf(-fabsf(x)));
}

__global__ __launch_bounds__(256) void k_loss(const float* __restrict__ inputs,
                                              const float* __restrict__ targets,
                                              const int*   __restrict__ anchor,
                                              const int*   __restrict__ dist) {
    int n = blockIdx.y;
    int s = blockIdx.x * 256 + threadIdx.x;

    float eq = 0.f, un = 0.f, ne = 0.f, nu = 0.f;

    if (s < SS) {
        int cnt    = g_total[n];
        int minlen = max(cnt, 1);
        int r      = anchor[n * SS + s] % minlen;
        int sel    = (cnt > 0) ? g_list[n * HW + r] : 0;

        float th = g_theta[n * HW + sel];
        float sn, cs;
        sincosf(th, &sn, &cs);
        int row_a = sel >> 10, col_a = sel & 1023;

        int lin[4];
#pragma unroll
        for (int j = 0; j < 4; j++) {
            int   d  = dist[((size_t)n * 4 + j) * SS + s];        // 0..18
            float fd = (float)(d + 2) * ((j < 2) ? -1.f : 1.f);   // sign [-,-,+,+]
            int cc = col_a + (int)rintf(fd * cs);                 // round-half-even
            int rr = row_a + (int)rintf(fd * sn);
            cc = min(max(cc, 0), WW - 1);
            rr = min(max(rr, 0), HH - 1);
            lin[j] = rr * WW + cc;
        }

        const float* inp = inputs  + (size_t)n * HW;
        const float* tgt = targets + (size_t)n * HW;
        float iv[4], lt[4], m[4];
#pragma unroll
        for (int j = 0; j < 4; j++) {
            iv[j] = inp[lin[j]];
            float t = tgt[lin[j]];
            m[j]  = (t > -1e-8f) ? 1.f : 0.f;
            lt[j] = logf(fmaxf(t, 1e-8f));
        }

        // thresholds: match jnp's f32 promotion: log(f32(1.03)), log(f32(1/1.03 in f64))
        const float up = logf((float)(1.0 + 0.03));
        const float lo = logf((float)(1.0 / (1.0 + 0.03)));

#pragma unroll
        for (int p = 0; p < 3; p++) {
            int a = p, b = p + 1;
            float lr   = lt[a] - lt[b];
            float cm   = m[a] * m[b];
            float diff = iv[a] - iv[b];
            bool  meq  = (lr < up) && (lr > lo);
            if (meq) {
                float ad  = fabsf(diff);
                float sl1 = (ad < 1.f) ? 0.5f * diff * diff : ad - 0.5f;
                eq += sl1 * cm;
                ne += cm;
            } else {
                float lab = (lr >= up) ? 1.f : -1.f;
                un += softplus_f(-diff * lab) * cm;
                nu += cm;
            }
        }
    }

    // block reduce (deterministic), write per-block partial
    __shared__ float4 sm[256];
    sm[threadIdx.x] = make_float4(eq, un, ne, nu);
    __syncthreads();
    for (int o = 128; o > 0; o >>= 1) {
        if (threadIdx.x < o) {
            sm[threadIdx.x].x += sm[threadIdx.x + o].x;
            sm[threadIdx.x].y += sm[threadIdx.x + o].y;
            sm[threadIdx.x].z += sm[threadIdx.x + o].z;
            sm[threadIdx.x].w += sm[threadIdx.x + o].w;
        }
        __syncthreads();
    }
    if (threadIdx.x == 0) g_part4[n][blockIdx.x] = sm[0];
}

// ---------------------------------------------------------------------------
__global__ __launch_bounds__(128) void k_final(float* __restrict__ out) {
    __shared__ float4 sh[128];
    int t = threadIdx.x;
    float total = 0.f;
    for (int n = 0; n < NIMG; n++) {
        sh[t] = g_part4[n][t];     // entries >= NBLK_S are zero from k_init
        __syncthreads();
        for (int o = 64; o > 0; o >>= 1) {
            if (t < o) {
                sh[t].x += sh[t + o].x;
                sh[t].y += sh[t + o].y;
                sh[t].z += sh[t + o].z;
                sh[t].w += sh[t + o].w;
            }
            __syncthreads();
        }
        if (t == 0) {
            float4 a = sh[0];
            total += a.x / fmaxf(a.z, 1.f) + a.y / fmaxf(a.w, 1.f);   // ALPHA = 1
        }
        __syncthreads();
    }
    if (t == 0) out[0] = total / (float)NIMG;
}

// ---------------------------------------------------------------------------
extern "C" void kernel_launch(void* const* d_in, const int* in_sizes, int n_in,
                              void* d_out, int out_size) {
    const float* inputs  = (const float*)d_in[0];   // [N,1,H,W]
    const float* targets = (const float*)d_in[1];   // [N,1,H,W]
    const float* images  = (const float*)d_in[2];   // [N,3,H,W]
    const int*   anchor  = (const int*)  d_in[3];   // [N,S]
    const int*   dist    = (const int*)  d_in[4];   // [N,4,S]
    float*       out     = (float*)d_out;

    k_init<<<1, 1024>>>();
    k_sobel<<<dim3(HW / 256, NIMG), 256>>>(images);
    k_rowcount<<<dim3(HH, NIMG), 1024>>>();
    k_rowscan<<<NIMG, 1024>>>();
    k_compact<<<dim3(HH, NIMG), 1024>>>();
    k_loss<<<dim3(NBLK_S, NIMG), 256>>>(inputs, targets, anchor, dist);
    k_final<<<1, 128>>>(out);
}

// round 2
// speedup vs baseline: 1.1582x; 1.1582x over previous
#include <cuda_runtime.h>
#include <math.h>

#define NIMG 8
#define HH   768
#define WW   1024
#define HW   (HH * WW)
#define SS   30000
#define NBLK_S ((SS + 255) / 256)      // 118 blocks per image for loss

#define SB_ROWS 8                       // rows per sobel-max block
#define SB_BLK  (HH / SB_ROWS)          // 96 blocks per image
#define TILE_ROWS 4                     // rows per compact tile
#define TILES_PER_IMG (HH / TILE_ROWS)  // 192
#define NTILES (NIMG * TILES_PER_IMG)   // 1536

// ---------------- device scratch (static, no runtime alloc) ----------------
__device__ int                g_list [NIMG * HW];          // compacted edge indices
__device__ float              g_bmax [NIMG * SB_BLK];      // per-block edge maxima
__device__ int                g_total[NIMG];               // edge count per image
__device__ unsigned long long g_state[NTILES];             // lookback: (status<<32)|value
__device__ unsigned           g_ticket;
__device__ float4             g_part4[NIMG][NBLK_S];       // loss partials

// ---------------------------------------------------------------------------
// Sobel edge magnitude at interior pixel (y,x) of channel-0 plane g.
// Identical expression used in all kernels -> identical fp results.
__device__ __forceinline__ float sobel_e(const float* __restrict__ g, int y, int x,
                                         float* gx_out, float* gy_out) {
    const float* r0 = g + (y - 1) * WW;
    const float* r1 = g + (y    ) * WW;
    const float* r2 = g + (y + 1) * WW;
    float a = r0[x - 1], b = r0[x], c = r0[x + 1];
    float d = r1[x - 1],            f = r1[x + 1];
    float p = r2[x - 1], q = r2[x], s = r2[x + 1];
    float gx = (c - a) + 2.f * (f - d) + (s - p);
    float gy = (a + 2.f * b + c) - (p + 2.f * q + s);
    *gx_out = gx; *gy_out = gy;
    return sqrtf(gx * gx + gy * gy + 1e-6f);
}

// ---------------------------------------------------------------------------
// Pass 1: per-block edge maxima (no edge/theta stores). Also resets the
// lookback state + ticket for the following compact kernel.
__global__ __launch_bounds__(256) void k_sobelmax(const float* __restrict__ images) {
    int n  = blockIdx.y;
    int b  = blockIdx.x;                 // 0..95
    int bid = n * SB_BLK + b;            // 0..767
    // reset lookback machinery (visible to k_compact via kernel boundary)
    if (threadIdx.x < 2) g_state[bid * 2 + threadIdx.x] = 0ULL;
    if (bid == 0 && threadIdx.x == 0) g_ticket = 0u;

    const float* g = images + (size_t)n * 3 * HW;
    int rowbase = b * SB_ROWS;

    float mx = 0.f;
    for (int i = threadIdx.x; i < SB_ROWS * WW; i += 256) {
        int y = rowbase + (i >> 10);
        int x = i & 1023;
        if (y >= 1 && y < HH - 1 && x >= 1 && x < WW - 1) {
            float gx, gy;
            float e = sobel_e(g, y, x, &gx, &gy);
            mx = fmaxf(mx, e);
        }
    }
    __shared__ float smax[256];
    smax[threadIdx.x] = mx;
    __syncthreads();
    for (int o = 128; o > 0; o >>= 1) {
        if (threadIdx.x < o) smax[threadIdx.x] = fmaxf(smax[threadIdx.x], smax[threadIdx.x + o]);
        __syncthreads();
    }
    if (threadIdx.x == 0) g_bmax[bid] = smax[0];
}

// ---------------------------------------------------------------------------
// Pass 2: fused threshold + stable (raster-order) compaction via decoupled
// lookback. One tile = 4 rows. Edge recomputed from images (L2-hot).
__global__ __launch_bounds__(1024) void k_compact(const float* __restrict__ images) {
    __shared__ int   staging[TILE_ROWS * WW];   // 16 KB
    __shared__ int   cntw[32], woff[32];
    __shared__ int   s_tile, s_rowtot, s_exc;
    __shared__ float s_thr;
    __shared__ float smax[128];

    int tid  = threadIdx.x;
    int lane = tid & 31, wid = tid >> 5;

    if (tid == 0) s_tile = (int)atomicAdd(&g_ticket, 1u);
    __syncthreads();
    int tile = s_tile;
    int n = tile / TILES_PER_IMG;
    int t = tile % TILES_PER_IMG;

    // reduce 96 per-block maxima -> threshold
    smax[tid & 127] = 0.f;                       // threads 0..127 cover slots
    __syncthreads();
    if (tid < SB_BLK) smax[tid] = g_bmax[n * SB_BLK + tid];
    __syncthreads();
    if (tid < 64) smax[tid] = fmaxf(smax[tid], smax[tid + 64]);
    __syncthreads();
    if (tid < 32) {
        float m = fmaxf(smax[tid], smax[tid + 32]);
        for (int o = 16; o > 0; o >>= 1) m = fmaxf(m, __shfl_down_sync(0xffffffffu, m, o));
        if (tid == 0) s_thr = m * 0.1f;
    }
    __syncthreads();
    float thr = s_thr;

    const float* g = images + (size_t)n * 3 * HW;
    int col = tid;                               // 1024 threads = 1024 cols
    int tile_off = 0;

    for (int r = 0; r < TILE_ROWS; r++) {
        int row = t * TILE_ROWS + r;
        int flag = 0;
        if (row >= 1 && row < HH - 1 && col >= 1 && col < WW - 1) {
            float gx, gy;
            float e = sobel_e(g, row, col, &gx, &gy);
            flag = (e >= thr) ? 1 : 0;
        }
        unsigned ball = __ballot_sync(0xffffffffu, flag);
        int wprefix = __popc(ball & ((1u << lane) - 1u));
        if (lane == 0) cntw[wid] = __popc(ball);
        __syncthreads();
        if (wid == 0) {
            int c = cntw[lane];
            int inc = c;
            for (int o = 1; o < 32; o <<= 1) {
                int u = __shfl_up_sync(0xffffffffu, inc, o);
                if (lane >= o) inc += u;
            }
            woff[lane] = inc - c;
            if (lane == 31) s_rowtot = inc;
        }
        __syncthreads();
        if (flag) staging[tile_off + woff[wid] + wprefix] = row * WW + col;
        tile_off += s_rowtot;
        __syncthreads();
    }
    int agg = tile_off;

    // publish + lookback (thread 0)
    if (tid == 0) {
        if (t == 0) {
            atomicExch(&g_state[tile], (2ULL << 32) | (unsigned)agg);
            s_exc = 0;
        } else {
            atomicExch(&g_state[tile], (1ULL << 32) | (unsigned)agg);
            int exc = 0;
            int j = tile - 1;
            while (true) {
                unsigned long long sv = atomicAdd(&g_state[j], 0ULL);
                unsigned st = (unsigned)(sv >> 32);
                if (st == 0u) continue;            // predecessor not published yet
                exc += (int)(sv & 0xffffffffu);
                if (st == 2u) break;
                j--;
            }
            atomicExch(&g_state[tile], (2ULL << 32) | (unsigned)(exc + agg));
            s_exc = exc;
        }
        if (t == TILES_PER_IMG - 1) g_total[n] = s_exc + agg;
    }
    __syncthreads();

    int exc = s_exc;
    int* dst = g_list + (size_t)n * HW + exc;
    for (int i = tid; i < agg; i += 1024) dst[i] = staging[i];   // coalesced
}

// ---------------------------------------------------------------------------
__device__ __forceinline__ float softplus_f(float x) {
    return fmaxf(x, 0.f) + log1pf(expf(-fabsf(x)));
}

__global__ __launch_bounds__(256) void k_loss(const float* __restrict__ inputs,
                                              const float* __restrict__ targets,
                                              const float* __restrict__ images,
                                              const int*   __restrict__ anchor,
                                              const int*   __restrict__ dist) {
    int n = blockIdx.y;
    int s = blockIdx.x * 256 + threadIdx.x;

    float eq = 0.f, un = 0.f, ne = 0.f, nu = 0.f;

    if (s < SS) {
        int cnt    = g_total[n];
        int minlen = max(cnt, 1);
        int r      = anchor[n * SS + s] % minlen;
        int sel    = g_list[n * HW + r];        // cnt >= 1 always (max pixel qualifies)

        // recompute theta at sel (interior guaranteed: border has e=0 < thr)
        const float* g = images + (size_t)n * 3 * HW;
        int row_a = sel >> 10, col_a = sel & 1023;
        float gx, gy;
        sobel_e(g, row_a, col_a, &gx, &gy);
        float th = atan2f(gy, gx);
        float sn, cs;
        sincosf(th, &sn, &cs);

        int lin[4];
#pragma unroll
        for (int j = 0; j < 4; j++) {
            int   d  = dist[((size_t)n * 4 + j) * SS + s];       // 0..18
            float fd = (float)(d + 2) * ((j < 2) ? -1.f : 1.f);  // sign [-,-,+,+]
            int cc = col_a + (int)rintf(fd * cs);                // round-half-even
            int rr = row_a + (int)rintf(fd * sn);
            cc = min(max(cc, 0), WW - 1);
            rr = min(max(rr, 0), HH - 1);
            lin[j] = rr * WW + cc;
        }

        const float* inp = inputs  + (size_t)n * HW;
        const float* tgt = targets + (size_t)n * HW;
        float iv[4], lt[4], m[4];
#pragma unroll
        for (int j = 0; j < 4; j++) {
            iv[j] = inp[lin[j]];
            float tv = tgt[lin[j]];
            m[j]  = (tv > -1e-8f) ? 1.f : 0.f;
            lt[j] = logf(fmaxf(tv, 1e-8f));
        }

        const float up = logf((float)(1.0 + 0.03));
        const float lo = logf((float)(1.0 / (1.0 + 0.03)));

#pragma unroll
        for (int p = 0; p < 3; p++) {
            float lr   = lt[p] - lt[p + 1];
            float cm   = m[p] * m[p + 1];
            float diff = iv[p] - iv[p + 1];
            bool  meq  = (lr < up) && (lr > lo);
            if (meq) {
                float ad  = fabsf(diff);
                float sl1 = (ad < 1.f) ? 0.5f * diff * diff : ad - 0.5f;
                eq += sl1 * cm;
                ne += cm;
            } else {
                float lab = (lr >= up) ? 1.f : -1.f;
                un += softplus_f(-diff * lab) * cm;
                nu += cm;
            }
        }
    }

    __shared__ float4 sm[256];
    sm[threadIdx.x] = make_float4(eq, un, ne, nu);
    __syncthreads();
    for (int o = 128; o > 0; o >>= 1) {
        if (threadIdx.x < o) {
            sm[threadIdx.x].x += sm[threadIdx.x + o].x;
            sm[threadIdx.x].y += sm[threadIdx.x + o].y;
            sm[threadIdx.x].z += sm[threadIdx.x + o].z;
            sm[threadIdx.x].w += sm[threadIdx.x + o].w;
        }
        __syncthreads();
    }
    if (threadIdx.x == 0) g_part4[n][blockIdx.x] = sm[0];
}

// ---------------------------------------------------------------------------
__global__ __launch_bounds__(128) void k_final(float* __restrict__ out) {
    __shared__ float4 sh[128];
    int t = threadIdx.x;
    float total = 0.f;
    for (int n = 0; n < NIMG; n++) {
        sh[t] = (t < NBLK_S) ? g_part4[n][t] : make_float4(0.f, 0.f, 0.f, 0.f);
        __syncthreads();
        for (int o = 64; o > 0; o >>= 1) {
            if (t < o) {
                sh[t].x += sh[t + o].x;
                sh[t].y += sh[t + o].y;
                sh[t].z += sh[t + o].z;
                sh[t].w += sh[t + o].w;
            }
            __syncthreads();
        }
        if (t == 0) {
            float4 a = sh[0];
            total += a.x / fmaxf(a.z, 1.f) + a.y / fmaxf(a.w, 1.f);
        }
        __syncthreads();
    }
    if (t == 0) out[0] = total / (float)NIMG;
}

// ---------------------------------------------------------------------------
extern "C" void kernel_launch(void* const* d_in, const int* in_sizes, int n_in,
                              void* d_out, int out_size) {
    const float* inputs  = (const float*)d_in[0];   // [N,1,H,W]
    const float* targets = (const float*)d_in[1];   // [N,1,H,W]
    const float* images  = (const float*)d_in[2];   // [N,3,H,W]
    const int*   anchor  = (const int*)  d_in[3];   // [N,S]
    const int*   dist    = (const int*)  d_in[4];   // [N,4,S]
    float*       out     = (float*)d_out;

    k_sobelmax<<<dim3(SB_BLK, NIMG), 256>>>(images);
    k_compact <<<NTILES, 1024>>>(images);
    k_loss    <<<dim3(NBLK_S, NIMG), 256>>>(inputs, targets, images, anchor, dist);
    k_final   <<<1, 128>>>(out);
}

// round 4
// speedup vs baseline: 1.3863x; 1.1970x over previous
#include <cuda_runtime.h>
#include <math.h>

#define NIMG 8
#define HH   768
#define WW   1024
#define HW   (HH * WW)
#define SS   30000
#define NBLK_S ((SS + 255) / 256)      // 118 loss blocks per image
#define NLOSS  (NIMG * NBLK_S)          // 944

#define SB_ROWS 8                       // rows per sobel-max block
#define SB_BLK  (HH / SB_ROWS)          // 96 blocks per image
#define TILE_ROWS 4                     // rows per compact tile
#define TILES_PER_IMG (HH / TILE_ROWS)  // 192
#define NTILES (NIMG * TILES_PER_IMG)   // 1536

// ---------------- device scratch (static, no runtime alloc) ----------------
__device__ int                g_list [NIMG * HW];          // compacted edge indices
__device__ float              g_bmax [NIMG * SB_BLK];      // per-block edge maxima
__device__ float              g_thr  [NIMG];               // per-image threshold
__device__ unsigned           g_imgcnt[NIMG];              // sobelmax completion ctr
__device__ int                g_total[NIMG];               // edge count per image
__device__ unsigned long long g_state[NTILES];             // lookback: (status<<32)|value
__device__ unsigned           g_ticket;                    // compact tile ticket
__device__ float4             g_part4[NIMG][NBLK_S];       // loss partials
__device__ unsigned           g_losscnt;                   // loss completion ctr

// ---------------------------------------------------------------------------
__device__ __forceinline__ float sobel_e(const float* __restrict__ g, int y, int x,
                                         float* gx_out, float* gy_out) {
    const float* r0 = g + (y - 1) * WW;
    const float* r1 = g + (y    ) * WW;
    const float* r2 = g + (y + 1) * WW;
    float a = r0[x - 1], b = r0[x], c = r0[x + 1];
    float d = r1[x - 1],            f = r1[x + 1];
    float p = r2[x - 1], q = r2[x], s = r2[x + 1];
    float gx = (c - a) + 2.f * (f - d) + (s - p);
    float gy = (a + 2.f * b + c) - (p + 2.f * q + s);
    *gx_out = gx; *gy_out = gy;
    return sqrtf(gx * gx + gy * gy + 1e-6f);
}

// ---------------------------------------------------------------------------
// Pass 1: per-block edge maxima; last block per image reduces -> g_thr[n].
// Also resets lookback states for the following compact kernel.
__global__ __launch_bounds__(256) void k_sobelmax(const float* __restrict__ images) {
    int n   = blockIdx.y;
    int b   = blockIdx.x;                // 0..95
    int bid = n * SB_BLK + b;            // 0..767
    if (threadIdx.x < 2) g_state[bid * 2 + threadIdx.x] = 0ULL;

    const float* g = images + (size_t)n * 3 * HW;
    int rowbase = b * SB_ROWS;
    bool interior = (rowbase >= 1) && (rowbase + SB_ROWS <= HH - 1);

    float mx = 0.f;
    if (interior) {
        // uniform path: only x-border predicate per pixel
        for (int i = threadIdx.x; i < SB_ROWS * WW; i += 256) {
            int y = rowbase + (i >> 10);
            int x = i & 1023;
            if (x >= 1 && x < WW - 1) {
                float gx, gy;
                mx = fmaxf(mx, sobel_e(g, y, x, &gx, &gy));
            }
        }
    } else {
        for (int i = threadIdx.x; i < SB_ROWS * WW; i += 256) {
            int y = rowbase + (i >> 10);
            int x = i & 1023;
            if (y >= 1 && y < HH - 1 && x >= 1 && x < WW - 1) {
                float gx, gy;
                mx = fmaxf(mx, sobel_e(g, y, x, &gx, &gy));
            }
        }
    }

    __shared__ float smax[256];
    __shared__ int   s_last;
    smax[threadIdx.x] = mx;
    __syncthreads();
    for (int o = 128; o > 0; o >>= 1) {
        if (threadIdx.x < o) smax[threadIdx.x] = fmaxf(smax[threadIdx.x], smax[threadIdx.x + o]);
        __syncthreads();
    }
    if (threadIdx.x == 0) {
        g_bmax[bid] = smax[0];
        __threadfence();
        unsigned old = atomicAdd(&g_imgcnt[n], 1u);
        s_last = (old == SB_BLK - 1);
    }
    __syncthreads();
    if (s_last) {
        if (threadIdx.x == 0) g_imgcnt[n] = 0u;          // reset for next replay
        __threadfence();
        float v = (threadIdx.x < SB_BLK) ? g_bmax[n * SB_BLK + threadIdx.x] : 0.f;
        smax[threadIdx.x] = v;
        __syncthreads();
        for (int o = 128; o > 0; o >>= 1) {
            if (threadIdx.x < o) smax[threadIdx.x] = fmaxf(smax[threadIdx.x], smax[threadIdx.x + o]);
            __syncthreads();
        }
        if (threadIdx.x == 0) g_thr[n] = smax[0] * 0.1f;
    }
}

// ---------------------------------------------------------------------------
// Pass 2: fused threshold + stable compaction, warp-parallel decoupled lookback.
__global__ __launch_bounds__(1024) void k_compact(const float* __restrict__ images) {
    __shared__ int staging[TILE_ROWS * WW];   // 16 KB
    __shared__ int cntw[32], woff[32];
    __shared__ int s_tile, s_rowtot, s_exc;

    int tid  = threadIdx.x;
    int lane = tid & 31, wid = tid >> 5;

    if (tid == 0) {
        unsigned tk = atomicAdd(&g_ticket, 1u);
        s_tile = (int)tk;
        if (tk == NTILES - 1) g_ticket = 0u;             // reset for next replay
    }
    __syncthreads();
    int tile = s_tile;
    int n = tile / TILES_PER_IMG;
    int t = tile % TILES_PER_IMG;

    float thr = g_thr[n];
    const float* g = images + (size_t)n * 3 * HW;
    int col = tid;
    int tile_off = 0;

    for (int r = 0; r < TILE_ROWS; r++) {
        int row = t * TILE_ROWS + r;
        int flag = 0;
        if (row >= 1 && row < HH - 1 && col >= 1 && col < WW - 1) {
            float gx, gy;
            float e = sobel_e(g, row, col, &gx, &gy);
            flag = (e >= thr) ? 1 : 0;
        }
        unsigned ball = __ballot_sync(0xffffffffu, flag);
        int wprefix = __popc(ball & ((1u << lane) - 1u));
        if (lane == 0) cntw[wid] = __popc(ball);
        __syncthreads();
        if (wid == 0) {
            int c = cntw[lane];
            int inc = c;
            for (int o = 1; o < 32; o <<= 1) {
                int u = __shfl_up_sync(0xffffffffu, inc, o);
                if (lane >= o) inc += u;
            }
            woff[lane] = inc - c;
            if (lane == 31) s_rowtot = inc;
        }
        __syncthreads();
        if (flag) staging[tile_off + woff[wid] + wprefix] = row * WW + col;
        tile_off += s_rowtot;
        __syncthreads();
    }
    int agg = tile_off;

    // publish + warp-parallel lookback (warp 0)
    if (wid == 0) {
        if (t == 0) {
            if (lane == 0) {
                atomicExch(&g_state[tile], (2ULL << 32) | (unsigned)agg);
                s_exc = 0;
                if (t == TILES_PER_IMG - 1) g_total[n] = agg;
            }
        } else {
            if (lane == 0) atomicExch(&g_state[tile], (1ULL << 32) | (unsigned)agg);
            __syncwarp();
            int exc = 0;
            int j = tile - 1;
            while (true) {
                int idx = j - lane;
                unsigned long long sv;
                unsigned st;
                do {
                    sv = (idx >= 0) ? atomicAdd(&g_state[idx], 0ULL) : (2ULL << 32);
                    st = (unsigned)(sv >> 32);
                } while (__ballot_sync(0xffffffffu, st == 0u) != 0u);
                unsigned b2 = __ballot_sync(0xffffffffu, st == 2u);
                int v = (int)(sv & 0xffffffffu);
                int contrib;
                if (b2) {
                    int l2 = __ffs(b2) - 1;                 // closest inclusive prefix
                    contrib = (lane <= l2) ? v : 0;
                } else {
                    contrib = v;                            // all aggregates
                }
                for (int o = 16; o > 0; o >>= 1)
                    contrib += __shfl_down_sync(0xffffffffu, contrib, o);
                contrib = __shfl_sync(0xffffffffu, contrib, 0);
                exc += contrib;
                if (b2) break;
                j -= 32;
            }
            if (lane == 0) {
                atomicExch(&g_state[tile], (2ULL << 32) | (unsigned)(exc + agg));
                s_exc = exc;
                if (t == TILES_PER_IMG - 1) g_total[n] = exc + agg;
            }
        }
    }
    __syncthreads();

    int* dst = g_list + (size_t)n * HW + s_exc;
    for (int i = tid; i < agg; i += 1024) dst[i] = staging[i];
}

// ---------------------------------------------------------------------------
__device__ __forceinline__ float softplus_f(float x) {
    return fmaxf(x, 0.f) + log1pf(expf(-fabsf(x)));
}

__global__ __launch_bounds__(256) void k_loss(const float* __restrict__ inputs,
                                              const float* __restrict__ targets,
                                              const float* __restrict__ images,
                                              const int*   __restrict__ anchor,
                                              const int*   __restrict__ dist,
                                              float*       __restrict__ out) {
    int n = blockIdx.y;
    int s = blockIdx.x * 256 + threadIdx.x;

    float eq = 0.f, un = 0.f, ne = 0.f, nu = 0.f;

    if (s < SS) {
        int cnt = g_total[n];                   // >= 1 always (max pixel qualifies)
        int r   = anchor[n * SS + s] % cnt;
        int sel = g_list[n * HW + r];

        const float* g = images + (size_t)n * 3 * HW;
        int row_a = sel >> 10, col_a = sel & 1023;
        float gx, gy;
        sobel_e(g, row_a, col_a, &gx, &gy);     // sel is interior (border e=0 < thr)
        float th = atan2f(gy, gx);
        float sn, cs;
        sincosf(th, &sn, &cs);

        int lin[4];
#pragma unroll
        for (int j = 0; j < 4; j++) {
            int   d  = dist[((size_t)n * 4 + j) * SS + s];       // 0..18
            float fd = (float)(d + 2) * ((j < 2) ? -1.f : 1.f);
            int cc = col_a + (int)rintf(fd * cs);
            int rr = row_a + (int)rintf(fd * sn);
            cc = min(max(cc, 0), WW - 1);
            rr = min(max(rr, 0), HH - 1);
            lin[j] = rr * WW + cc;
        }

        const float* inp = inputs  + (size_t)n * HW;
        const float* tgt = targets + (size_t)n * HW;
        float iv[4], lt[4], m[4];
#pragma unroll
        for (int j = 0; j < 4; j++) {
            iv[j] = inp[lin[j]];
            float tv = tgt[lin[j]];
            m[j]  = (tv > -1e-8f) ? 1.f : 0.f;
            lt[j] = logf(fmaxf(tv, 1e-8f));
        }

        const float up = logf((float)(1.0 + 0.03));
        const float lo = logf((float)(1.0 / (1.0 + 0.03)));

#pragma unroll
        for (int p = 0; p < 3; p++) {
            float lr   = lt[p] - lt[p + 1];
            float cm   = m[p] * m[p + 1];
            float diff = iv[p] - iv[p + 1];
            bool  meq  = (lr < up) && (lr > lo);
            if (meq) {
                float ad  = fabsf(diff);
                float sl1 = (ad < 1.f) ? 0.5f * diff * diff : ad - 0.5f;
                eq += sl1 * cm;
                ne += cm;
            } else {
                float lab = (lr >= up) ? 1.f : -1.f;
                un += softplus_f(-diff * lab) * cm;
                nu += cm;
            }
        }
    }

    // block reduce -> per-block partial
    __shared__ float4 sm[256];
    __shared__ int    s_last;
    __shared__ float  s_img[8];
    sm[threadIdx.x] = make_float4(eq, un, ne, nu);
    __syncthreads();
    for (int o = 128; o > 0; o >>= 1) {
        if (threadIdx.x < o) {
            sm[threadIdx.x].x += sm[threadIdx.x + o].x;
            sm[threadIdx.x].y += sm[threadIdx.x + o].y;
            sm[threadIdx.x].z += sm[threadIdx.x + o].z;
            sm[threadIdx.x].w += sm[threadIdx.x + o].w;
        }
        __syncthreads();
    }
    if (threadIdx.x == 0) {
        g_part4[n][blockIdx.x] = sm[0];
        __threadfence();
        unsigned old = atomicAdd(&g_losscnt, 1u);
        s_last = (old == NLOSS - 1);
    }
    __syncthreads();

    // last block: fused final reduction (8 warps, one image each)
    if (s_last) {
        if (threadIdx.x == 0) g_losscnt = 0u;            // reset for next replay
        __threadfence();
        int w = threadIdx.x >> 5, lane = threadIdx.x & 31;
        float4 acc = make_float4(0.f, 0.f, 0.f, 0.f);
        for (int i = lane; i < NBLK_S; i += 32) {
            float4 p = g_part4[w][i];
            acc.x += p.x; acc.y += p.y; acc.z += p.z; acc.w += p.w;
        }
        for (int o = 16; o > 0; o >>= 1) {
            acc.x += __shfl_down_sync(0xffffffffu, acc.x, o);
            acc.y += __shfl_down_sync(0xffffffffu, acc.y, o);
            acc.z += __shfl_down_sync(0xffffffffu, acc.z, o);
            acc.w += __shfl_down_sync(0xffffffffu, acc.w, o);
        }
        if (lane == 0)
            s_img[w] = acc.x / fmaxf(acc.z, 1.f) + acc.y / fmaxf(acc.w, 1.f);
        __syncthreads();
        if (threadIdx.x == 0) {
            float total = 0.f;
            for (int i = 0; i < 8; i++) total += s_img[i];
            out[0] = total / (float)NIMG;
        }
    }
}

// ---------------------------------------------------------------------------
extern "C" void kernel_launch(void* const* d_in, const int* in_sizes, int n_in,
                              void* d_out, int out_size) {
    const float* inputs  = (const float*)d_in[0];   // [N,1,H,W]
    const float* targets = (const float*)d_in[1];   // [N,1,H,W]
    const float* images  = (const float*)d_in[2];   // [N,3,H,W]
    const int*   anchor  = (const int*)  d_in[3];   // [N,S]
    const int*   dist    = (const int*)  d_in[4];   // [N,4,S]
    float*       out     = (float*)d_out;

    k_sobelmax<<<dim3(SB_BLK, NIMG), 256>>>(images);
    k_compact <<<NTILES, 1024>>>(images);
    k_loss    <<<dim3(NBLK_S, NIMG), 256>>>(inputs, targets, images, anchor, dist, out);
}